// round 4
// baseline (speedup 1.0000x reference)
#include <cuda_runtime.h>
#include <cuda_bf16.h>

// Quantumnet, warp-per-batch-element, statevector (1024 f32) in registers as
// 16 x f32x2 packs per lane. Wire->bit map:
//   lane bits L4..L0  = wires 0,2,4,6,8 ; pack bits P3..P0 = wires 1,3,5,7 ;
//   pack slot (lo/hi) = wire 9.
// RYs in tan-half-angle form with globally deferred cosines.
// Even CNOTs (ctrl=lane bit, tgt=pack/slot bit) are NEVER executed: they are
// deferred as a per-lane XOR relabeling of register indices (mask m, slot s).
// Since every layer applies the same even-CNOT pattern, the mask toggles with
// period 2: layers alternate A (under mask) / B (clean, mask cancelled).

#define WARPS_PER_BLOCK 8
#define THREADS (WARPS_PER_BLOCK * 32)
typedef unsigned long long u64;

__device__ __forceinline__ u64 pk2(float lo, float hi) {
    u64 r; asm("mov.b64 %0,{%1,%2};" : "=l"(r) : "f"(lo), "f"(hi)); return r;
}
__device__ __forceinline__ void upk2(u64 x, float& lo, float& hi) {
    asm("mov.b64 {%0,%1},%2;" : "=f"(lo), "=f"(hi) : "l"(x));
}
__device__ __forceinline__ u64 fma2(u64 a, u64 b, u64 c) {
    u64 d; asm("fma.rn.f32x2 %0,%1,%2,%3;" : "=l"(d) : "l"(a), "l"(b), "l"(c)); return d;
}
__device__ __forceinline__ u64 mul2(u64 a, u64 b) {
    u64 d; asm("mul.rn.f32x2 %0,%1,%2;" : "=l"(d) : "l"(a), "l"(b)); return d;
}
__device__ __forceinline__ u64 add2(u64 a, u64 b) {
    u64 d; asm("add.rn.f32x2 %0,%1,%2;" : "=l"(d) : "l"(a), "l"(b)); return d;
}
__device__ __forceinline__ u64 shfl64(u64 x, int m) {
    return __shfl_xor_sync(0xffffffffu, x, m);
}
__device__ __forceinline__ float tanh_apx(float x) {
    float y; asm("tanh.approx.f32 %0,%1;" : "=f"(y) : "f"(x)); return y;
}
__device__ __forceinline__ u64 wsum2(u64 x) {
#pragma unroll
    for (int m = 16; m; m >>= 1) x = add2(x, shfl64(x, m));
    return x;
}

// ---- clean (mask = 0) ops ----

template <int Q>
__device__ __forceinline__ void ry_lane(u64* v, u64 ts) {
#pragma unroll
    for (int r = 0; r < 16; r++) {
        u64 p = shfl64(v[r], 1 << Q);
        v[r] = fma2(ts, p, v[r]);
    }
}

template <int Q, int CMASK>
__device__ __forceinline__ void cnot_ry(u64* v, u64 ts) {
#pragma unroll
    for (int r = 0; r < 16; r++) {
        u64 old = v[r];
        u64 p = shfl64(old, 1 << Q);
        if (r & CMASK) v[r] = fma2(ts, old, p);
        else           v[r] = fma2(ts, p, old);
    }
}

template <int PM>
__device__ __forceinline__ void ry_pack(u64* v, u64 tp, u64 tn) {
#pragma unroll
    for (int r = 0; r < 16; r++) {
        if (!(r & PM)) {
            const int r1 = r | PM;
            u64 X = v[r], Y = v[r1];
            v[r]  = fma2(tn, Y, X);
            v[r1] = fma2(tp, X, Y);
        }
    }
}

__device__ __forceinline__ void ry_slot(u64* v, float t) {
#pragma unroll
    for (int r = 0; r < 16; r++) {
        float lo, hi; upk2(v[r], lo, hi);
        float nlo = fmaf(-t, hi, lo);
        float nhi = fmaf(t, lo, hi);
        v[r] = pk2(nlo, nhi);
    }
}

// ---- masked (mask = P, slot = L0) ops ----

// Fused odd-CNOT+RY under mask: shuffle lane bit Q, partner physical index
// r^DELTA (DELTA = the mask bit controlled by lane bit Q). Coefficients:
// out = a*old + b*p for r&CBIT==0, (b,a) for r&CBIT==1 (a,b preselected per
// lane from cond = Lbit of CBIT's controlling lane bit).
template <int Q, int DELTA, int CBIT>
__device__ __forceinline__ void cnot_ry_m(u64* v, u64 a, u64 b) {
#pragma unroll
    for (int r0 = 0; r0 < 16; r0++) {
        if (!(r0 & DELTA)) {
            const int r1 = r0 | DELTA;
            u64 o0 = v[r0], o1 = v[r1];
            u64 p0 = shfl64(o1, 1 << Q);   // partner physical r0^DELTA
            u64 p1 = shfl64(o0, 1 << Q);   // partner physical r1^DELTA
            v[r0] = (r0 & CBIT) ? fma2(b, o0, mul2(a, p0)) : fma2(a, o0, mul2(b, p0));
            v[r1] = (r1 & CBIT) ? fma2(b, o1, mul2(a, p1)) : fma2(a, o1, mul2(b, p1));
        }
    }
}

// Masked fused CNOT(w7->w8)+RY(w8): shuffle lane bit 0; pack delta 0, but the
// slot mask differs between partners -> consume the two 32-bit halves crossed.
__device__ __forceinline__ void cnot_ry0_m(u64* v, u64 a, u64 b) {
#pragma unroll
    for (int r = 0; r < 16; r++) {
        float lo, hi; upk2(v[r], lo, hi);
        float plo = __shfl_xor_sync(0xffffffffu, hi, 1);
        float phi = __shfl_xor_sync(0xffffffffu, lo, 1);
        u64 p = pk2(plo, phi);
        v[r] = (r & 1) ? fma2(b, v[r], mul2(a, p)) : fma2(a, v[r], mul2(b, p));
    }
}

// Masked plain RY on lane bit Q with partner physical index r^DELTA.
template <int Q, int DELTA>
__device__ __forceinline__ void ry_lane_m(u64* v, u64 ts) {
#pragma unroll
    for (int r0 = 0; r0 < 16; r0++) {
        if (!(r0 & DELTA)) {
            const int r1 = r0 | DELTA;
            u64 o0 = v[r0], o1 = v[r1];
            u64 p0 = shfl64(o1, 1 << Q);
            u64 p1 = shfl64(o0, 1 << Q);
            v[r0] = fma2(ts, p0, o0);
            v[r1] = fma2(ts, p1, o1);
        }
    }
}

__global__ __launch_bounds__(THREADS, 4)
void qnet_kernel(const float* __restrict__ x,      // [B,512]
                 const float* __restrict__ Wred,   // [10,512]
                 const float* __restrict__ bred,   // [10]
                 const float* __restrict__ qp,     // [150]
                 const float* __restrict__ Wpost,  // [2,10]
                 const float* __restrict__ bpost,  // [2]
                 float* __restrict__ out,          // [B,2]
                 int B) {
    __shared__ u64 sW2[5 * 512];          // packed (Wred[2q], Wred[2q+1])
    __shared__ u64 stp[60], stn[60];      // (t,t), (-t,-t) per fixed RY
    __shared__ float st1[60];             // scalar t per fixed RY
    __shared__ float scc[60];             // cosines for F product
    __shared__ float sbred[10], sWp[20], sbp[2], sF[1];

    const int tid = threadIdx.x;
    for (int i = tid; i < 5 * 512; i += THREADS) {
        int q = i >> 9, col = i & 511;
        sW2[i] = pk2(Wred[(2 * q) * 512 + col], Wred[(2 * q + 1) * 512 + col]);
    }
    if (tid < 60) {
        int k = tid / 10, w = tid % 10;
        float s, c;
        sincosf(qp[(k + 1) * 10 + w] * 0.5f, &s, &c);
        float t = s / c;
        stp[tid] = pk2(t, t); stn[tid] = pk2(-t, -t); st1[tid] = t; scc[tid] = c;
    }
    if (tid >= 64 && tid < 74)   sbred[tid - 64] = bred[tid - 64];
    if (tid >= 96 && tid < 116)  sWp[tid - 96] = Wpost[tid - 96];
    if (tid >= 128 && tid < 130) sbp[tid - 128] = bpost[tid - 128];
    __syncthreads();
    if (tid == 0) {
        float f = 1.0f;
#pragma unroll
        for (int i = 0; i < 60; i++) f *= scc[i];
        sF[0] = f;
    }
    __syncthreads();

    const int lane = tid & 31;
    const int b = blockIdx.x * WARPS_PER_BLOCK + (tid >> 5);
    if (b >= B) return;

    const bool L4 = (lane >> 4) & 1, L3 = (lane >> 3) & 1, L2 = (lane >> 2) & 1,
               L1 = (lane >> 1) & 1, L0 = lane & 1;
    const u64 ONE = pk2(1.0f, 1.0f);

    // ---- front layer: pre = x[b] @ Wred^T + bred; th = tanh(pre)*pi/2 ----
    const float* xr = x + (size_t)b * 512;
    u64 acc2[5];
#pragma unroll
    for (int q = 0; q < 5; q++) acc2[q] = 0ull;
#pragma unroll
    for (int j = 0; j < 16; j++) {
        float xv = xr[lane + 32 * j];
        u64 xv2 = pk2(xv, xv);
#pragma unroll
        for (int q = 0; q < 5; q++)
            acc2[q] = fma2(xv2, sW2[q * 512 + lane + 32 * j], acc2[q]);
    }
    float th[10];
#pragma unroll
    for (int q = 0; q < 5; q++) {
        u64 r2 = wsum2(acc2[q]);
        float p0, p1; upk2(r2, p0, p1);
        th[2 * q]     = tanh_apx(p0 + sbred[2 * q]) * 1.5707963267948966f;
        th[2 * q + 1] = tanh_apx(p1 + sbred[2 * q + 1]) * 1.5707963267948966f;
    }

    // ---- product state: H-layer + data RY layer (exact), scaled by F ----
    float gl[5][2], gp[4][2], g9[2];
#pragma unroll
    for (int q = 0; q < 5; q++) {
        float s, c; __sincosf(th[2 * q] * 0.5f, &s, &c);
        gl[q][0] = (c - s) * 0.7071067811865476f;
        gl[q][1] = (c + s) * 0.7071067811865476f;
    }
#pragma unroll
    for (int q = 0; q < 4; q++) {
        float s, c; __sincosf(th[2 * q + 1] * 0.5f, &s, &c);
        gp[q][0] = (c - s) * 0.7071067811865476f;
        gp[q][1] = (c + s) * 0.7071067811865476f;
    }
    {
        float s, c; __sincosf(th[9] * 0.5f, &s, &c);
        g9[0] = (c - s) * 0.7071067811865476f;
        g9[1] = (c + s) * 0.7071067811865476f;
    }
    float F = sF[0] * (L4 ? gl[0][1] : gl[0][0]);
    F *= (L3 ? gl[1][1] : gl[1][0]);
    F *= (L2 ? gl[2][1] : gl[2][0]);
    F *= (L1 ? gl[3][1] : gl[3][0]);
    F *= (L0 ? gl[4][1] : gl[4][0]);
    float hiP[4], loP[4];
#pragma unroll
    for (int i = 0; i < 4; i++) {
        hiP[i] = gp[0][(i >> 1) & 1] * gp[1][i & 1];   // wires 1,3
        loP[i] = gp[2][(i >> 1) & 1] * gp[3][i & 1];   // wires 5,7
    }
    u64 G9F = pk2(F * g9[0], F * g9[1]);
    u64 v[16];
#pragma unroll
    for (int r = 0; r < 16; r++) {
        float m = hiP[r >> 2] * loP[r & 3];
        v[r] = mul2(pk2(m, m), G9F);
    }

    // ---- 6 entangling layers as 3 x (masked A + clean B) ----
#pragma unroll 1
    for (int kk = 0; kk < 3; kk++) {
        // ======== Layer A: even CNOTs deferred into mask m=P, s=L0 ========
        {
            const u64* TP = stp + (2 * kk) * 10;
            const u64* TN = stn + (2 * kk) * 10;
            // CNOT(w1->w2)+RY(w2): Q=3, DELTA=4 (bit4 ctrl'd by L3), CBIT=8 (ctrl'd by L4)
            { u64 ts = L3 ? TP[2] : TN[2];
              u64 a = L4 ? ts : ONE, bb = L4 ? ONE : ts;
              cnot_ry_m<3, 4, 8>(v, a, bb); }
            // CNOT(w3->w4)+RY(w4): Q=2, DELTA=2, CBIT=4 (ctrl'd by L3)
            { u64 ts = L2 ? TP[4] : TN[4];
              u64 a = L3 ? ts : ONE, bb = L3 ? ONE : ts;
              cnot_ry_m<2, 2, 4>(v, a, bb); }
            // CNOT(w5->w6)+RY(w6): Q=1, DELTA=1, CBIT=2 (ctrl'd by L2)
            { u64 ts = L1 ? TP[6] : TN[6];
              u64 a = L2 ? ts : ONE, bb = L2 ? ONE : ts;
              cnot_ry_m<1, 1, 2>(v, a, bb); }
            // CNOT(w7->w8)+RY(w8): Q=0, pack DELTA=0, slot crossed, CBIT=1 (ctrl'd by L1)
            { u64 ts = L0 ? TP[8] : TN[8];
              u64 a = L1 ? ts : ONE, bb = L1 ? ONE : ts;
              cnot_ry0_m(v, a, bb); }
            // RY(w0): Q=4, DELTA=8 (bit8 ctrl'd by L4)
            { u64 ts = L4 ? TP[0] : TN[0]; ry_lane_m<4, 8>(v, ts); }
            // RY on pack wires: role swap iff mask bit set
            { u64 etp = L4 ? TN[1] : TP[1], etn = L4 ? TP[1] : TN[1]; ry_pack<8>(v, etp, etn); }
            { u64 etp = L3 ? TN[3] : TP[3], etn = L3 ? TP[3] : TN[3]; ry_pack<4>(v, etp, etn); }
            { u64 etp = L2 ? TN[5] : TP[5], etn = L2 ? TP[5] : TN[5]; ry_pack<2>(v, etp, etn); }
            { u64 etp = L1 ? TN[7] : TP[7], etn = L1 ? TP[7] : TN[7]; ry_pack<1>(v, etp, etn); }
            // RY(w9): slot roles swapped iff s=L0
            { float t = st1[(2 * kk) * 10 + 9]; ry_slot(v, L0 ? -t : t); }
        }
        // ======== Layer B: even CNOTs cancel the mask (free); clean ========
        {
            const u64* TP = stp + (2 * kk + 1) * 10;
            const u64* TN = stn + (2 * kk + 1) * 10;
            cnot_ry<3, 8>(v, L3 ? TP[2] : TN[2]);   // (w1->w2)+RY w2
            cnot_ry<2, 4>(v, L2 ? TP[4] : TN[4]);   // (w3->w4)+RY w4
            cnot_ry<1, 2>(v, L1 ? TP[6] : TN[6]);   // (w5->w6)+RY w6
            cnot_ry<0, 1>(v, L0 ? TP[8] : TN[8]);   // (w7->w8)+RY w8
            ry_lane<4>(v, L4 ? TP[0] : TN[0]);      // RY w0
            ry_pack<8>(v, TP[1], TN[1]);
            ry_pack<4>(v, TP[3], TN[3]);
            ry_pack<2>(v, TP[5], TN[5]);
            ry_pack<1>(v, TP[7], TN[7]);
            ry_slot(v, st1[(2 * kk + 1) * 10 + 9]);
        }
    }

    // ---- <Z_w> + output projection, fused (mask is back to 0) ----
    const u64 P1 = pk2(1.0f, 1.0f), M1 = pk2(-1.0f, -1.0f);
    u64 S2 = 0ull, A8 = 0ull, A4 = 0ull, A2 = 0ull, A1 = 0ull;
#pragma unroll
    for (int r = 0; r < 16; r++) {
        u64 sq = mul2(v[r], v[r]);
        S2 = add2(S2, sq);
        A8 = fma2((r & 8) ? M1 : P1, sq, A8);
        A4 = fma2((r & 4) ? M1 : P1, sq, A4);
        A2 = fma2((r & 2) ? M1 : P1, sq, A2);
        A1 = fma2((r & 1) ? M1 : P1, sq, A1);
    }
    float sl, sh; upk2(S2, sl, sh);
    float Sv = sl + sh;
    float t9 = sl - sh;
    float l8, h8; upk2(A8, l8, h8); float t1 = l8 + h8;
    float l4, h4; upk2(A4, l4, h4); float t3 = l4 + h4;
    float l2, h2; upk2(A2, l2, h2); float t5 = l2 + h2;
    float l1, h1; upk2(A1, l1, h1); float t7 = l1 + h1;
    float t0 = L4 ? -Sv : Sv;
    float t2 = L3 ? -Sv : Sv;
    float t4 = L2 ? -Sv : Sv;
    float t6 = L1 ? -Sv : Sv;
    float t8 = L0 ? -Sv : Sv;

    float y0 = sWp[0] * t0 + sWp[1] * t1 + sWp[2] * t2 + sWp[3] * t3 + sWp[4] * t4
             + sWp[5] * t5 + sWp[6] * t6 + sWp[7] * t7 + sWp[8] * t8 + sWp[9] * t9;
    float y1 = sWp[10] * t0 + sWp[11] * t1 + sWp[12] * t2 + sWp[13] * t3 + sWp[14] * t4
             + sWp[15] * t5 + sWp[16] * t6 + sWp[17] * t7 + sWp[18] * t8 + sWp[19] * t9;
    u64 y2 = wsum2(pk2(y0, y1));
    if (lane == 0) {
        float r0, r1; upk2(y2, r0, r1);
        out[2 * (size_t)b + 0] = r0 + sbp[0];
        out[2 * (size_t)b + 1] = r1 + sbp[1];
    }
}

extern "C" void kernel_launch(void* const* d_in, const int* in_sizes, int n_in,
                              void* d_out, int out_size) {
    const float* x     = (const float*)d_in[0];
    const float* Wred  = (const float*)d_in[1];
    const float* bred  = (const float*)d_in[2];
    const float* qp    = (const float*)d_in[3];
    const float* Wpost = (const float*)d_in[4];
    const float* bpost = (const float*)d_in[5];
    float* out = (float*)d_out;

    int B = in_sizes[0] / 512;
    int blocks = (B + WARPS_PER_BLOCK - 1) / WARPS_PER_BLOCK;
    qnet_kernel<<<blocks, THREADS>>>(x, Wred, bred, qp, Wpost, bpost, out, B);
}

// round 5
// speedup vs baseline: 1.4613x; 1.4613x over previous
#include <cuda_runtime.h>
#include <cuda_bf16.h>

// Quantumnet, warp-per-batch-element, statevector (1024 f32) in registers as
// 16 x f32x2 packs per lane. Wire->bit map:
//   lane bits L4..L0  = wires 0,2,4,6,8 ; pack bits P3..P0 = wires 1,3,5,7 ;
//   pack slot (lo/hi) = wire 9.
// RYs use tan-half-angle with deferred cosine: out = a +- t*b, and the global
// factor F = prod(cos) over all 60 fixed rotations is folded into the initial
// product state (batch-independent). One fma2 per packed update.
// R5: identical algorithm to R3 (best), plus launch_bounds(256,4) to force
// regs<=64 and recover 4 CTAs/SM occupancy.

#define WARPS_PER_BLOCK 8
#define THREADS (WARPS_PER_BLOCK * 32)
typedef unsigned long long u64;

__device__ __forceinline__ u64 pk2(float lo, float hi) {
    u64 r; asm("mov.b64 %0,{%1,%2};" : "=l"(r) : "f"(lo), "f"(hi)); return r;
}
__device__ __forceinline__ void upk2(u64 x, float& lo, float& hi) {
    asm("mov.b64 {%0,%1},%2;" : "=f"(lo), "=f"(hi) : "l"(x));
}
__device__ __forceinline__ u64 fma2(u64 a, u64 b, u64 c) {
    u64 d; asm("fma.rn.f32x2 %0,%1,%2,%3;" : "=l"(d) : "l"(a), "l"(b), "l"(c)); return d;
}
__device__ __forceinline__ u64 mul2(u64 a, u64 b) {
    u64 d; asm("mul.rn.f32x2 %0,%1,%2;" : "=l"(d) : "l"(a), "l"(b)); return d;
}
__device__ __forceinline__ u64 add2(u64 a, u64 b) {
    u64 d; asm("add.rn.f32x2 %0,%1,%2;" : "=l"(d) : "l"(a), "l"(b)); return d;
}
__device__ __forceinline__ u64 shfl64(u64 x, int m) {
    return __shfl_xor_sync(0xffffffffu, x, m);
}
__device__ __forceinline__ float tanh_apx(float x) {
    float y; asm("tanh.approx.f32 %0,%1;" : "=f"(y) : "f"(x)); return y;
}
__device__ __forceinline__ u64 wsum2(u64 x) {
#pragma unroll
    for (int m = 16; m; m >>= 1) x = add2(x, shfl64(x, m));
    return x;
}

// RY on lane bit Q: out = v + t_s * partner
template <int Q>
__device__ __forceinline__ void ry_lane(u64* v, u64 ts) {
#pragma unroll
    for (int r = 0; r < 16; r++) {
        u64 p = shfl64(v[r], 1 << Q);
        v[r] = fma2(ts, p, v[r]);
    }
}

// Fused CNOT(ctrl = pack bit CMASK, tgt = lane bit Q) + RY(tgt wire), tan form
template <int Q, int CMASK>
__device__ __forceinline__ void cnot_ry(u64* v, u64 ts) {
#pragma unroll
    for (int r = 0; r < 16; r++) {
        u64 old = v[r];
        u64 p = shfl64(old, 1 << Q);
        if (r & CMASK) v[r] = fma2(ts, old, p);
        else           v[r] = fma2(ts, p, old);
    }
}

// RY on pack bit PM: X' = X - tY ; Y' = Y + tX
template <int PM>
__device__ __forceinline__ void ry_pack(u64* v, u64 tp, u64 tn) {
#pragma unroll
    for (int r = 0; r < 16; r++) {
        if (!(r & PM)) {
            const int r1 = r | PM;
            u64 X = v[r], Y = v[r1];
            v[r]  = fma2(tn, Y, X);
            v[r1] = fma2(tp, X, Y);
        }
    }
}

// RY on slot bit (wire 9): lo' = lo - t*hi ; hi' = hi + t*lo
__device__ __forceinline__ void ry_slot(u64* v, float t) {
#pragma unroll
    for (int r = 0; r < 16; r++) {
        float lo, hi; upk2(v[r], lo, hi);
        float nlo = fmaf(-t, hi, lo);
        float nhi = fmaf(t, lo, hi);
        v[r] = pk2(nlo, nhi);
    }
}

// CNOT ctrl = lane bit QC, tgt = pack bit PM: predicated pack swaps
template <int QC, int PM>
__device__ __forceinline__ void cnot_lp(u64* v, int lane) {
    const bool ct = (lane >> QC) & 1;
#pragma unroll
    for (int r = 0; r < 16; r++) {
        if (!(r & PM)) {
            const int r1 = r | PM;
            u64 a = v[r], b = v[r1];
            v[r]  = ct ? b : a;
            v[r1] = ct ? a : b;
        }
    }
}

// CNOT ctrl = lane bit 0 (wire 8), tgt = slot (wire 9)
__device__ __forceinline__ void cnot_ls(u64* v, int lane) {
    const bool ct = lane & 1;
#pragma unroll
    for (int r = 0; r < 16; r++) {
        float lo, hi; upk2(v[r], lo, hi);
        float nlo = ct ? hi : lo;
        float nhi = ct ? lo : hi;
        v[r] = pk2(nlo, nhi);
    }
}

__global__ __launch_bounds__(THREADS, 4)
void qnet_kernel(const float* __restrict__ x,      // [B,512]
                 const float* __restrict__ Wred,   // [10,512]
                 const float* __restrict__ bred,   // [10]
                 const float* __restrict__ qp,     // [150]
                 const float* __restrict__ Wpost,  // [2,10]
                 const float* __restrict__ bpost,  // [2]
                 float* __restrict__ out,          // [B,2]
                 int B) {
    __shared__ u64 sW2[5 * 512];          // packed (Wred[2q], Wred[2q+1])
    __shared__ u64 stab[120];             // [0..59]=(t,t), [60..119]=(-t,-t)
    __shared__ float st1[60];             // scalar t per fixed RY
    __shared__ float scc[60];             // cosines for F product
    __shared__ float sbred[10], sWp[20], sbp[2], sF[1];

    const int tid = threadIdx.x;
    for (int i = tid; i < 5 * 512; i += THREADS) {
        int q = i >> 9, col = i & 511;
        sW2[i] = pk2(Wred[(2 * q) * 512 + col], Wred[(2 * q + 1) * 512 + col]);
    }
    if (tid < 60) {
        int k = tid / 10, w = tid % 10;
        float s, c;
        sincosf(qp[(k + 1) * 10 + w] * 0.5f, &s, &c);
        float t = s / c;
        stab[tid] = pk2(t, t); stab[tid + 60] = pk2(-t, -t);
        st1[tid] = t; scc[tid] = c;
    }
    if (tid >= 64 && tid < 74)   sbred[tid - 64] = bred[tid - 64];
    if (tid >= 96 && tid < 116)  sWp[tid - 96] = Wpost[tid - 96];
    if (tid >= 128 && tid < 130) sbp[tid - 128] = bpost[tid - 128];
    __syncthreads();
    if (tid == 0) {
        float f = 1.0f;
#pragma unroll
        for (int i = 0; i < 60; i++) f *= scc[i];
        sF[0] = f;
    }
    __syncthreads();

    const int lane = tid & 31;
    const int b = blockIdx.x * WARPS_PER_BLOCK + (tid >> 5);
    if (b >= B) return;

    // ---- front layer: pre = x[b] @ Wred^T + bred; th = tanh(pre)*pi/2 ----
    const float* xr = x + (size_t)b * 512;
    u64 acc2[5];
#pragma unroll
    for (int q = 0; q < 5; q++) acc2[q] = 0ull;
#pragma unroll
    for (int j = 0; j < 16; j++) {
        float xv = xr[lane + 32 * j];
        u64 xv2 = pk2(xv, xv);
#pragma unroll
        for (int q = 0; q < 5; q++)
            acc2[q] = fma2(xv2, sW2[q * 512 + lane + 32 * j], acc2[q]);
    }
    float th[10];
#pragma unroll
    for (int q = 0; q < 5; q++) {
        u64 r2 = wsum2(acc2[q]);
        float p0, p1; upk2(r2, p0, p1);
        th[2 * q]     = tanh_apx(p0 + sbred[2 * q]) * 1.5707963267948966f;
        th[2 * q + 1] = tanh_apx(p1 + sbred[2 * q + 1]) * 1.5707963267948966f;
    }

    // ---- product state: H-layer + data RY layer (exact), scaled by F ----
    float gl[5][2], gp[4][2], g9[2];
#pragma unroll
    for (int q = 0; q < 5; q++) {
        float s, c; __sincosf(th[2 * q] * 0.5f, &s, &c);
        gl[q][0] = (c - s) * 0.7071067811865476f;
        gl[q][1] = (c + s) * 0.7071067811865476f;
    }
#pragma unroll
    for (int q = 0; q < 4; q++) {
        float s, c; __sincosf(th[2 * q + 1] * 0.5f, &s, &c);
        gp[q][0] = (c - s) * 0.7071067811865476f;
        gp[q][1] = (c + s) * 0.7071067811865476f;
    }
    {
        float s, c; __sincosf(th[9] * 0.5f, &s, &c);
        g9[0] = (c - s) * 0.7071067811865476f;
        g9[1] = (c + s) * 0.7071067811865476f;
    }
    float F = sF[0] * ((lane & 16) ? gl[0][1] : gl[0][0]);
    F *= ((lane & 8) ? gl[1][1] : gl[1][0]);
    F *= ((lane & 4) ? gl[2][1] : gl[2][0]);
    F *= ((lane & 2) ? gl[3][1] : gl[3][0]);
    F *= ((lane & 1) ? gl[4][1] : gl[4][0]);
    float hiP[4], loP[4];
#pragma unroll
    for (int i = 0; i < 4; i++) {
        hiP[i] = gp[0][(i >> 1) & 1] * gp[1][i & 1];   // wires 1,3
        loP[i] = gp[2][(i >> 1) & 1] * gp[3][i & 1];   // wires 5,7
    }
    u64 G9F = pk2(F * g9[0], F * g9[1]);
    u64 v[16];
#pragma unroll
    for (int r = 0; r < 16; r++) {
        float m = hiP[r >> 2] * loP[r & 3];
        v[r] = mul2(pk2(m, m), G9F);
    }

    // ---- 6 entangling layers (tan-form RYs, deferred cosine) ----
#pragma unroll 1
    for (int k = 0; k < 6; k++) {
        const u64* TP = stab + k * 10;
        const u64* TN = TP + 60;
        // even CNOTs: pure register selects
        cnot_lp<4, 8>(v, lane);   // (0->1)
        cnot_lp<3, 4>(v, lane);   // (2->3)
        cnot_lp<2, 2>(v, lane);   // (4->5)
        cnot_lp<1, 1>(v, lane);   // (6->7)
        cnot_ls(v, lane);         // (8->9)
        // odd CNOTs fused with RY on their even-wire target (1 shfl + 1 fma each)
        cnot_ry<3, 8>(v, ((lane >> 3) & 1) ? TP[2] : TN[2]);  // (1->2)+RY w2
        cnot_ry<2, 4>(v, ((lane >> 2) & 1) ? TP[4] : TN[4]);  // (3->4)+RY w4
        cnot_ry<1, 2>(v, ((lane >> 1) & 1) ? TP[6] : TN[6]);  // (5->6)+RY w6
        cnot_ry<0, 1>(v, (lane & 1) ? TP[8] : TN[8]);         // (7->8)+RY w8
        // remaining RYs
        ry_lane<4>(v, ((lane >> 4) & 1) ? TP[0] : TN[0]);     // RY w0
        ry_pack<8>(v, TP[1], TN[1]);
        ry_pack<4>(v, TP[3], TN[3]);
        ry_pack<2>(v, TP[5], TN[5]);
        ry_pack<1>(v, TP[7], TN[7]);
        ry_slot(v, st1[k * 10 + 9]);                          // RY w9
    }

    // ---- <Z_w> + output projection, fused ----
    const u64 P1 = pk2(1.0f, 1.0f), M1 = pk2(-1.0f, -1.0f);
    u64 S2 = 0ull, A8 = 0ull, A4 = 0ull, A2 = 0ull, A1 = 0ull;
#pragma unroll
    for (int r = 0; r < 16; r++) {
        u64 sq = mul2(v[r], v[r]);
        S2 = add2(S2, sq);
        A8 = fma2((r & 8) ? M1 : P1, sq, A8);
        A4 = fma2((r & 4) ? M1 : P1, sq, A4);
        A2 = fma2((r & 2) ? M1 : P1, sq, A2);
        A1 = fma2((r & 1) ? M1 : P1, sq, A1);
    }
    float sl, sh; upk2(S2, sl, sh);
    float Sv = sl + sh;
    float t9 = sl - sh;
    float l8, h8; upk2(A8, l8, h8); float t1 = l8 + h8;
    float l4, h4; upk2(A4, l4, h4); float t3 = l4 + h4;
    float l2, h2; upk2(A2, l2, h2); float t5 = l2 + h2;
    float l1, h1; upk2(A1, l1, h1); float t7 = l1 + h1;
    float t0 = (lane & 16) ? -Sv : Sv;
    float t2 = (lane & 8)  ? -Sv : Sv;
    float t4 = (lane & 4)  ? -Sv : Sv;
    float t6 = (lane & 2)  ? -Sv : Sv;
    float t8 = (lane & 1)  ? -Sv : Sv;

    float y0 = sWp[0] * t0 + sWp[1] * t1 + sWp[2] * t2 + sWp[3] * t3 + sWp[4] * t4
             + sWp[5] * t5 + sWp[6] * t6 + sWp[7] * t7 + sWp[8] * t8 + sWp[9] * t9;
    float y1 = sWp[10] * t0 + sWp[11] * t1 + sWp[12] * t2 + sWp[13] * t3 + sWp[14] * t4
             + sWp[15] * t5 + sWp[16] * t6 + sWp[17] * t7 + sWp[18] * t8 + sWp[19] * t9;
    u64 y2 = wsum2(pk2(y0, y1));
    if (lane == 0) {
        float r0, r1; upk2(y2, r0, r1);
        out[2 * (size_t)b + 0] = r0 + sbp[0];
        out[2 * (size_t)b + 1] = r1 + sbp[1];
    }
}

extern "C" void kernel_launch(void* const* d_in, const int* in_sizes, int n_in,
                              void* d_out, int out_size) {
    const float* x     = (const float*)d_in[0];
    const float* Wred  = (const float*)d_in[1];
    const float* bred  = (const float*)d_in[2];
    const float* qp    = (const float*)d_in[3];
    const float* Wpost = (const float*)d_in[4];
    const float* bpost = (const float*)d_in[5];
    float* out = (float*)d_out;

    int B = in_sizes[0] / 512;
    int blocks = (B + WARPS_PER_BLOCK - 1) / WARPS_PER_BLOCK;
    qnet_kernel<<<blocks, THREADS>>>(x, Wred, bred, qp, Wpost, bpost, out, B);
}